// round 15
// baseline (speedup 1.0000x reference)
#include <cuda_runtime.h>
#include <cstdint>

// NNUE HalfKP forward — single launch, producer/consumer blocks.
//   Producers (blocks 0..1279): (64 kings x 20 slices of 32 rows). Stage tile
//     int32->int16 SMEM, bucket pairs, 8 warps x 4 pairs dense predicated-vadd2
//     accumulate -> g_part, then fence + per-sample counters. Block 0 also
//     pre-packs FC weights (wready flag).
//   Consumers (blocks 1280..): warp per sample; sleep until counter==40,
//     acquire, combine 40 partials + 2 king bias rows + input_bias
//     (mod 2^16 == ref astype(int16)), clip, FC1/FC2, output dot, atomicAdd;
//     last sample writes floor_div(total+out_b,16) as float and self-resets.
//
// Inputs (ALL integers widened to int32 by the harness):
//  0 piece_positions (B,640)  1 king_positions (B,2)  2 input_weights (64,641,256)
//  3 input_bias (256)  4 w1 (32,512)  5 b1 (32)  6 w2 (32,32)  7 b2 (32)
//  8 out_w (32)  9 out_b (1)        out: float32 (1)

#define NQ      20               // row slices
#define QR      32               // rows per slice
#define NPROD   (64 * NQ)        // producer blocks
#define MAXP    2048
#define MAXS    1024
#define BCAP    128
#define TARGET  (2 * NQ)         // partial stores per sample

__device__ uint4    g_part[NQ][MAXP * 32];   // packed-int16 partial sums (20 MB)
__device__ unsigned g_w1t[128 * 32];         // dp4a-packed w1, j-major [j*32+out]
__device__ int      g_w2t[32 * 32];          // w2 transposed [in*32+out]
__device__ int      g_scnt[MAXS];            // per-sample store counters (self-reset)
__device__ int      g_total;                 // self-reset
__device__ int      g_done;                  // self-reset
__device__ int      g_wready;                // sticky (weights constant across replays)

__global__ void __launch_bounds__(256, 4) hx_all(
    const int* __restrict__ W32,
    const int* __restrict__ pp,
    const int* __restrict__ kings,
    const int* __restrict__ w1,
    const int* __restrict__ w2,
    const int* __restrict__ bias,
    const int* __restrict__ b1,
    const int* __restrict__ b2,
    const int* __restrict__ ow,
    const int* __restrict__ ob,
    float* __restrict__ out,
    int B)
{
    __shared__ short    s_tile[QR * 256];   // 16 KB (producers)
    __shared__ int      s_bucket[BCAP];
    __shared__ int      s_cnt;
    __shared__ unsigned s_x[8][64];         // (consumers)
    __shared__ int      s_x1[8][32];

    const int warp = threadIdx.x >> 5;
    const int lane = threadIdx.x & 31;

    if (blockIdx.x < NPROD) {
        // ================= PRODUCER =================
        const int k = blockIdx.x & 63;
        const int q = blockIdx.x >> 6;

        if (blockIdx.x == 0) {
            for (int t = threadIdx.x; t < 32 * 128; t += 256) {
                const int o = t >> 7, j = t & 127;
                const int* p = w1 + t * 4;
                g_w1t[j * 32 + o] =
                    (unsigned)(p[0] & 0xff) | ((unsigned)(p[1] & 0xff) << 8) |
                    ((unsigned)(p[2] & 0xff) << 16) | ((unsigned)p[3] << 24);
            }
            for (int t = threadIdx.x; t < 32 * 32; t += 256)
                g_w2t[(t & 31) * 32 + (t >> 5)] = w2[t];
            __syncthreads();
            __threadfence();
            if (threadIdx.x == 0) atomicExch(&g_wready, 1);
        }
        if (threadIdx.x == 0) s_cnt = 0;

        // kings[] scan loads into registers (in flight during tile staging)
        const int P = 2 * B;
        int kv[8];
        int nk = 0;
        #pragma unroll
        for (int j = 0; j < 8; j++) {
            const int i = threadIdx.x + j * 256;
            if (i < P) { kv[nk] = kings[i]; nk++; }
        }

        // stage + narrow tile: rows [q*32, q*32+32) int32 -> int16 SMEM
        {
            const int4* src = (const int4*)(W32 + ((size_t)k * 641 + (size_t)q * QR) * 256);
            short4* dst = (short4*)s_tile;
            #pragma unroll
            for (int i = threadIdx.x; i < QR * 256 / 4; i += 256) {
                const int4 v = src[i];
                dst[i] = make_short4((short)v.x, (short)v.y, (short)v.z, (short)v.w);
            }
        }

        __syncthreads();
        for (int j = 0; j < nk; j++)
            if (kv[j] == k) {
                const int slot = atomicAdd(&s_cnt, 1);
                if (slot < BCAP) s_bucket[slot] = threadIdx.x + j * 256;
            }
        __syncthreads();

        const int cnt = min(s_cnt, BCAP);
        const char* tb = (const char*)s_tile + lane * 16;

        for (int gb = warp * 4; gb < cnt; gb += 32) {
            const int npair = min(4, cnt - gb);

            unsigned m[4];
            int pid[4];
            #pragma unroll
            for (int j = 0; j < 4; j++) {
                const bool valid = (j < npair);
                const int  p = s_bucket[valid ? (gb + j) : gb];
                pid[j] = p;
                const int* ppq = pp + (size_t)(p >> 1) * 640 + q * QR;
                const unsigned b = __ballot_sync(0xffffffffu, ppq[lane] != 0);
                m[j] = valid ? b : 0u;
            }

            unsigned acc[4][4];
            #pragma unroll
            for (int j = 0; j < 4; j++)
                acc[j][0] = acc[j][1] = acc[j][2] = acc[j][3] = 0u;

            #pragma unroll
            for (int r = 0; r < QR; r++) {
                const uint4 row = *(const uint4*)(tb + (r << 9));
                #pragma unroll
                for (int j = 0; j < 4; j++) {
                    if (m[j] & (1u << r)) {
                        acc[j][0] = __vadd2(acc[j][0], row.x);
                        acc[j][1] = __vadd2(acc[j][1], row.y);
                        acc[j][2] = __vadd2(acc[j][2], row.z);
                        acc[j][3] = __vadd2(acc[j][3], row.w);
                    }
                }
            }

            #pragma unroll
            for (int j = 0; j < 4; j++)
                if (j < npair)
                    g_part[q][pid[j] * 32 + lane] =
                        make_uint4(acc[j][0], acc[j][1], acc[j][2], acc[j][3]);

            // release: stores visible before counter bumps
            __threadfence();
            if (lane == 0) {
                #pragma unroll
                for (int j = 0; j < 4; j++)
                    if (j < npair) atomicAdd(&g_scnt[pid[j] >> 1], 1);
            }
        }
    } else {
        // ================= CONSUMER =================
        const int s = (blockIdx.x - NPROD) * 8 + warp;
        if (s >= B) return;

        // wait for all 40 partials of this sample
        if (lane == 0) {
            while (atomicAdd(&g_scnt[s], 0) < TARGET) __nanosleep(200);
            atomicSub(&g_scnt[s], TARGET);             // self-reset for replay
            while (atomicAdd(&g_wready, 0) == 0) __nanosleep(100);
        }
        __syncwarp();
        __threadfence();                               // acquire

        // combine 20 slices x 2 sides, two register batches of 10 loads
        unsigned a0 = 0, a1 = 0, a2 = 0, a3 = 0;
        #pragma unroll
        for (int h = 0; h < 4; h++) {
            uint4 r[10];
            #pragma unroll
            for (int i = 0; i < 10; i++) {
                const int q = (h >> 1) * 10 + (i >> 1) * 2 + (h & 1);
                const int side = i & 1;
                r[i] = g_part[q][(2 * s + side) * 32 + lane];
            }
            #pragma unroll
            for (int i = 0; i < 10; i++) {
                a0 = __vadd2(a0, r[i].x); a1 = __vadd2(a1, r[i].y);
                a2 = __vadd2(a2, r[i].z); a3 = __vadd2(a3, r[i].w);
            }
        }
        // per-king bias rows + input_bias
        const int k0 = kings[2 * s + 0];
        const int k1 = kings[2 * s + 1];
        const int4* br0 = (const int4*)(W32 + ((size_t)k0 * 641 + 640) * 256 + lane * 8);
        const int4* br1 = (const int4*)(W32 + ((size_t)k1 * 641 + 640) * 256 + lane * 8);
        const int4 u0 = br0[0], v0 = br0[1];
        const int4 u1 = br1[0], v1 = br1[1];
        const int4 bA = ((const int4*)bias)[lane * 2 + 0];
        const int4 bB = ((const int4*)bias)[lane * 2 + 1];
        a0 = __vadd2(a0, (unsigned)(u0.x & 0xffff) | ((unsigned)u0.y << 16));
        a1 = __vadd2(a1, (unsigned)(u0.z & 0xffff) | ((unsigned)u0.w << 16));
        a2 = __vadd2(a2, (unsigned)(v0.x & 0xffff) | ((unsigned)v0.y << 16));
        a3 = __vadd2(a3, (unsigned)(v0.z & 0xffff) | ((unsigned)v0.w << 16));
        a0 = __vadd2(a0, (unsigned)(u1.x & 0xffff) | ((unsigned)u1.y << 16));
        a1 = __vadd2(a1, (unsigned)(u1.z & 0xffff) | ((unsigned)u1.w << 16));
        a2 = __vadd2(a2, (unsigned)(v1.x & 0xffff) | ((unsigned)v1.y << 16));
        a3 = __vadd2(a3, (unsigned)(v1.z & 0xffff) | ((unsigned)v1.w << 16));
        a0 = __vadd2(a0, (unsigned)(bA.x & 0xffff) | ((unsigned)bA.y << 16));
        a1 = __vadd2(a1, (unsigned)(bA.z & 0xffff) | ((unsigned)bA.w << 16));
        a2 = __vadd2(a2, (unsigned)(bB.x & 0xffff) | ((unsigned)bB.y << 16));
        a3 = __vadd2(a3, (unsigned)(bB.z & 0xffff) | ((unsigned)bB.w << 16));

        // clip int16 -> [0,127], pack 8 int8 into 2 words
        unsigned accs[4] = {a0, a1, a2, a3};
        int c8[8];
        #pragma unroll
        for (int kk = 0; kk < 4; kk++) {
            int lo = (int)(short)(accs[kk] & 0xffffu);
            int hi = (int)(short)(accs[kk] >> 16);
            c8[2 * kk + 0] = min(max(lo, 0), 127);
            c8[2 * kk + 1] = min(max(hi, 0), 127);
        }
        s_x[warp][lane * 2 + 0] = (unsigned)c8[0] | ((unsigned)c8[1] << 8) |
                                  ((unsigned)c8[2] << 16) | ((unsigned)c8[3] << 24);
        s_x[warp][lane * 2 + 1] = (unsigned)c8[4] | ((unsigned)c8[5] << 8) |
                                  ((unsigned)c8[6] << 16) | ((unsigned)c8[7] << 24);
        __syncwarp();

        // FC1: lane = output unit; x512 = [x, x]; 4 independent dp4a chains
        int v1a = b1[lane], v1b = 0, v1c = 0, v1d = 0;
        #pragma unroll 8
        for (int j = 0; j < 64; j += 2) {
            const int x0 = (int)s_x[warp][j];
            const int x1 = (int)s_x[warp][j + 1];
            v1a = __dp4a(x0, (int)__ldg(&g_w1t[j * 32 + lane]),        v1a);
            v1b = __dp4a(x0, (int)__ldg(&g_w1t[(64 + j) * 32 + lane]), v1b);
            v1c = __dp4a(x1, (int)__ldg(&g_w1t[(j + 1) * 32 + lane]),  v1c);
            v1d = __dp4a(x1, (int)__ldg(&g_w1t[(65 + j) * 32 + lane]), v1d);
        }
        int v1s = (v1a + v1b) + (v1c + v1d);
        v1s >>= 6;
        v1s = min(max(v1s, 0), 127);
        s_x1[warp][lane] = v1s;
        __syncwarp();

        // FC2
        int v2a = b2[lane], v2b = 0;
        #pragma unroll 8
        for (int o = 0; o < 32; o += 2) {
            v2a += s_x1[warp][o]     * __ldg(&g_w2t[o * 32 + lane]);
            v2b += s_x1[warp][o + 1] * __ldg(&g_w2t[(o + 1) * 32 + lane]);
        }
        int v2 = v2a + v2b;
        v2 >>= 6;
        v2 = min(max(v2, 0), 127);

        int contrib = v2 * ow[lane];
        #pragma unroll
        for (int sh = 16; sh; sh >>= 1)
            contrib += __shfl_xor_sync(0xffffffffu, contrib, sh);

        if (lane == 0) {
            atomicAdd(&g_total, contrib);
            __threadfence();
            if (atomicAdd(&g_done, 1) == B - 1) {      // unique last sample
                const int tot = atomicAdd(&g_total, 0);
                out[0] = (float)((tot + ob[0]) >> 4);
                atomicExch(&g_total, 0);               // self-reset for replay
                atomicExch(&g_done, 0);
            }
        }
    }
}

extern "C" void kernel_launch(void* const* d_in, const int* in_sizes, int n_in,
                              void* d_out, int out_size) {
    const int B = in_sizes[0] / 640;
    const int cblocks = (B + 7) / 8;
    hx_all<<<NPROD + cblocks, 256>>>(
        (const int*)d_in[2],
        (const int*)d_in[0],
        (const int*)d_in[1],
        (const int*)d_in[4],
        (const int*)d_in[6],
        (const int*)d_in[3],
        (const int*)d_in[5],
        (const int*)d_in[7],
        (const int*)d_in[8],
        (const int*)d_in[9],
        (float*)d_out,
        B);
}

// round 16
// speedup vs baseline: 1.2808x; 1.2808x over previous
#include <cuda_runtime.h>
#include <cstdint>

// NNUE HalfKP forward — king-grouped, 2-kernel formulation (R10 phaseA).
//   phaseA: grid (64 kings x 20 slices of 32 rows), 16 KB tile, oc4.
//           8 warps x 4 pairs, dense predicated-vadd2 accumulate -> g_part.
//           Block (0,0) zeroes scalars + pre-packs FC weights.
//   phaseB: 256 blocks, two-stage. Stage 1: warp = one (sample,side) pair,
//           sums its 20 partials + its king bias row (packed int16) -> SMEM.
//           Stage 2: warps 0..3 combine both sides + input_bias (mod 2^16 ==
//           ref astype(int16)), clip, FC1/FC2 from packed-transposed weights,
//           output dot, atomicAdd; last block writes floor_div(total+out_b,16).
//
// Inputs (ALL integers widened to int32 by the harness):
//  0 piece_positions (B,640)  1 king_positions (B,2)  2 input_weights (64,641,256)
//  3 input_bias (256)  4 w1 (32,512)  5 b1 (32)  6 w2 (32,32)  7 b2 (32)
//  8 out_w (32)  9 out_b (1)        out: float32 (1)

#define NQ    20                 // row slices
#define QR    32                 // rows per slice
#define MAXP  2048               // max (sample,side) pairs (B <= 1024)
#define BCAP  128                // per-king bucket capacity (mean 32, sd 5.6)

__device__ uint4    g_part[NQ][MAXP * 32];   // packed-int16 partial sums (20 MB)
__device__ unsigned g_w1t[128 * 32];         // dp4a-packed w1, j-major [j*32+out]
__device__ int      g_w2t[32 * 32];          // w2 transposed [in*32+out]
__device__ int      g_total;
__device__ int      g_done;

// ---------------- phase A (identical to the 28.4us champion) ----------------
__global__ void __launch_bounds__(256, 4) hx_phaseA(
    const int* __restrict__ W32,
    const int* __restrict__ pp,
    const int* __restrict__ kings,
    const int* __restrict__ w1,
    const int* __restrict__ w2,
    int B)
{
    __shared__ short s_tile[QR * 256];    // 16 KB
    __shared__ int   s_bucket[BCAP];
    __shared__ int   s_cnt;

    const int k = blockIdx.x;
    const int q = blockIdx.y;

    if (k == 0 && q == 0) {
        if (threadIdx.x == 0) { g_total = 0; g_done = 0; }
        for (int t = threadIdx.x; t < 32 * 128; t += 256) {
            const int o = t >> 7, j = t & 127;
            const int* p = w1 + t * 4;
            g_w1t[j * 32 + o] =
                (unsigned)(p[0] & 0xff) | ((unsigned)(p[1] & 0xff) << 8) |
                ((unsigned)(p[2] & 0xff) << 16) | ((unsigned)p[3] << 24);
        }
        for (int t = threadIdx.x; t < 32 * 32; t += 256)
            g_w2t[(t & 31) * 32 + (t >> 5)] = w2[t];
    }
    if (threadIdx.x == 0) s_cnt = 0;

    // kings[] scan loads into registers (in flight during tile staging)
    const int P = 2 * B;
    int kv[8];
    int nk = 0;
    #pragma unroll
    for (int j = 0; j < 8; j++) {
        const int i = threadIdx.x + j * 256;
        if (i < P) { kv[nk] = kings[i]; nk++; }
    }

    // stage + narrow tile: rows [q*32, q*32+32) int32 -> int16 SMEM
    {
        const int4* src = (const int4*)(W32 + ((size_t)k * 641 + (size_t)q * QR) * 256);
        short4* dst = (short4*)s_tile;
        #pragma unroll
        for (int i = threadIdx.x; i < QR * 256 / 4; i += 256) {
            const int4 v = src[i];
            dst[i] = make_short4((short)v.x, (short)v.y, (short)v.z, (short)v.w);
        }
    }

    __syncthreads();
    for (int j = 0; j < nk; j++)
        if (kv[j] == k) {
            const int slot = atomicAdd(&s_cnt, 1);
            if (slot < BCAP) s_bucket[slot] = threadIdx.x + j * 256;
        }
    __syncthreads();

    const int cnt = min(s_cnt, BCAP);
    const int warp = threadIdx.x >> 5;
    const int lane = threadIdx.x & 31;
    const char* tb = (const char*)s_tile + lane * 16;   // lane covers 8 dims

    for (int gb = warp * 4; gb < cnt; gb += 32) {
        const int npair = min(4, cnt - gb);

        unsigned m[4];
        int pid[4];
        #pragma unroll
        for (int j = 0; j < 4; j++) {
            const bool valid = (j < npair);
            const int  p = s_bucket[valid ? (gb + j) : gb];
            pid[j] = p;
            const int* ppq = pp + (size_t)(p >> 1) * 640 + q * QR;
            const unsigned b = __ballot_sync(0xffffffffu, ppq[lane] != 0);
            m[j] = valid ? b : 0u;
        }

        unsigned acc[4][4];
        #pragma unroll
        for (int j = 0; j < 4; j++)
            acc[j][0] = acc[j][1] = acc[j][2] = acc[j][3] = 0u;

        #pragma unroll
        for (int r = 0; r < QR; r++) {
            const uint4 row = *(const uint4*)(tb + (r << 9));
            #pragma unroll
            for (int j = 0; j < 4; j++) {
                if (m[j] & (1u << r)) {
                    acc[j][0] = __vadd2(acc[j][0], row.x);
                    acc[j][1] = __vadd2(acc[j][1], row.y);
                    acc[j][2] = __vadd2(acc[j][2], row.z);
                    acc[j][3] = __vadd2(acc[j][3], row.w);
                }
            }
        }

        #pragma unroll
        for (int j = 0; j < 4; j++)
            if (j < npair)
                g_part[q][pid[j] * 32 + lane] =
                    make_uint4(acc[j][0], acc[j][1], acc[j][2], acc[j][3]);
    }
}

// ---------------- phase B: two-stage combine + FC + finalize ----------------
__global__ void __launch_bounds__(256, 1) hx_phaseB(
    const int* __restrict__ W32,
    const int* __restrict__ kings,
    const int* __restrict__ bias,
    const int* __restrict__ b1,
    const int* __restrict__ b2,
    const int* __restrict__ ow,
    const int* __restrict__ ob,
    float* __restrict__ out,
    int B, int nblocks)
{
    __shared__ uint4    s_acc[8][32];     // stage-1 per-side packed sums (4 KB)
    __shared__ unsigned s_x[4][64];
    __shared__ int      s_x1[4][32];
    __shared__ int      s_wsum[4];

    const int warp = threadIdx.x >> 5;
    const int lane = threadIdx.x & 31;

    // ---- stage 1: warp = one (sample,side) pair; 20 partials + king bias ----
    const int p = blockIdx.x * 8 + warp;   // pair id
    if (p < 2 * B) {
        uint4 r[20];
        #pragma unroll
        for (int q = 0; q < NQ; q++)
            r[q] = g_part[q][p * 32 + lane];
        const int kk = kings[p];
        const int4* br = (const int4*)(W32 + ((size_t)kk * 641 + 640) * 256 + lane * 8);
        const int4 u = br[0], v = br[1];

        unsigned a0 = (unsigned)(u.x & 0xffff) | ((unsigned)u.y << 16);
        unsigned a1 = (unsigned)(u.z & 0xffff) | ((unsigned)u.w << 16);
        unsigned a2 = (unsigned)(v.x & 0xffff) | ((unsigned)v.y << 16);
        unsigned a3 = (unsigned)(v.z & 0xffff) | ((unsigned)v.w << 16);
        #pragma unroll
        for (int i = 0; i < NQ; i++) {
            a0 = __vadd2(a0, r[i].x); a1 = __vadd2(a1, r[i].y);
            a2 = __vadd2(a2, r[i].z); a3 = __vadd2(a3, r[i].w);
        }
        s_acc[warp][lane] = make_uint4(a0, a1, a2, a3);
    }
    __syncthreads();

    // ---- stage 2: warps 0..3, sample = blockIdx*4 + warp ----
    int contrib = 0;
    const int s = blockIdx.x * 4 + warp;
    if (warp < 4 && s < B) {
        const uint4 rA = s_acc[2 * warp + 0][lane];
        const uint4 rB = s_acc[2 * warp + 1][lane];
        const int4 bA = ((const int4*)bias)[lane * 2 + 0];
        const int4 bB = ((const int4*)bias)[lane * 2 + 1];

        unsigned a0 = __vadd2(__vadd2(rA.x, rB.x),
                              (unsigned)(bA.x & 0xffff) | ((unsigned)bA.y << 16));
        unsigned a1 = __vadd2(__vadd2(rA.y, rB.y),
                              (unsigned)(bA.z & 0xffff) | ((unsigned)bA.w << 16));
        unsigned a2 = __vadd2(__vadd2(rA.z, rB.z),
                              (unsigned)(bB.x & 0xffff) | ((unsigned)bB.y << 16));
        unsigned a3 = __vadd2(__vadd2(rA.w, rB.w),
                              (unsigned)(bB.z & 0xffff) | ((unsigned)bB.w << 16));

        // clip int16 -> [0,127], pack 8 int8 into 2 words
        unsigned accs[4] = {a0, a1, a2, a3};
        int c8[8];
        #pragma unroll
        for (int kk = 0; kk < 4; kk++) {
            int lo = (int)(short)(accs[kk] & 0xffffu);
            int hi = (int)(short)(accs[kk] >> 16);
            c8[2 * kk + 0] = min(max(lo, 0), 127);
            c8[2 * kk + 1] = min(max(hi, 0), 127);
        }
        s_x[warp][lane * 2 + 0] = (unsigned)c8[0] | ((unsigned)c8[1] << 8) |
                                  ((unsigned)c8[2] << 16) | ((unsigned)c8[3] << 24);
        s_x[warp][lane * 2 + 1] = (unsigned)c8[4] | ((unsigned)c8[5] << 8) |
                                  ((unsigned)c8[6] << 16) | ((unsigned)c8[7] << 24);
        __syncwarp();

        // FC1: lane = output unit; x512 = [x, x]; 4 independent dp4a chains
        int v1a = b1[lane], v1b = 0, v1c = 0, v1d = 0;
        #pragma unroll 8
        for (int j = 0; j < 64; j += 2) {
            const int x0 = (int)s_x[warp][j];
            const int x1 = (int)s_x[warp][j + 1];
            v1a = __dp4a(x0, (int)__ldg(&g_w1t[j * 32 + lane]),        v1a);
            v1b = __dp4a(x0, (int)__ldg(&g_w1t[(64 + j) * 32 + lane]), v1b);
            v1c = __dp4a(x1, (int)__ldg(&g_w1t[(j + 1) * 32 + lane]),  v1c);
            v1d = __dp4a(x1, (int)__ldg(&g_w1t[(65 + j) * 32 + lane]), v1d);
        }
        int v1s = (v1a + v1b) + (v1c + v1d);
        v1s >>= 6;
        v1s = min(max(v1s, 0), 127);
        s_x1[warp][lane] = v1s;
        __syncwarp();

        // FC2
        int v2a = b2[lane], v2b = 0;
        #pragma unroll 8
        for (int o = 0; o < 32; o += 2) {
            v2a += s_x1[warp][o]     * __ldg(&g_w2t[o * 32 + lane]);
            v2b += s_x1[warp][o + 1] * __ldg(&g_w2t[(o + 1) * 32 + lane]);
        }
        int v2 = v2a + v2b;
        v2 >>= 6;
        v2 = min(max(v2, 0), 127);

        contrib = v2 * ow[lane];
        #pragma unroll
        for (int sh = 16; sh; sh >>= 1)
            contrib += __shfl_xor_sync(0xffffffffu, contrib, sh);
    }

    if (warp < 4 && lane == 0) s_wsum[warp] = contrib;
    __syncthreads();
    if (threadIdx.x == 0) {
        int t = 0;
        #pragma unroll
        for (int w = 0; w < 4; w++) t += s_wsum[w];
        atomicAdd(&g_total, t);
        __threadfence();
        if (atomicAdd(&g_done, 1) == nblocks - 1) {
            const int tot = atomicAdd(&g_total, 0);
            out[0] = (float)((tot + ob[0]) >> 4);
        }
    }
}

extern "C" void kernel_launch(void* const* d_in, const int* in_sizes, int n_in,
                              void* d_out, int out_size) {
    const int B = in_sizes[0] / 640;
    const int sblocks = (B + 3) / 4;

    hx_phaseA<<<dim3(64, NQ), 256>>>(
        (const int*)d_in[2], (const int*)d_in[0], (const int*)d_in[1],
        (const int*)d_in[4], (const int*)d_in[6], B);
    hx_phaseB<<<sblocks, 256>>>(
        (const int*)d_in[2],
        (const int*)d_in[1],
        (const int*)d_in[3],
        (const int*)d_in[5],
        (const int*)d_in[7],
        (const int*)d_in[8],
        (const int*)d_in[9],
        (float*)d_out,
        B, sblocks);
}